// round 11
// baseline (speedup 1.0000x reference)
#include <cuda_runtime.h>
#include <cuda_fp16.h>
#include <math.h>
#include <stdint.h>

#define N_TOK 8192
#define C_DIM 768
#define E_NUM 8
#define H_DIM 3072
#define NSEL  (2*N_TOK)
#define KC    64
#define MT    128          // M tile (sel rows per block)

// ---------------- device scratch (no runtime allocation) ----------------
__device__ int   g_counts[E_NUM];
__device__ int   g_tok [E_NUM*N_TOK];
__device__ int   g_hrow[E_NUM*N_TOK];
__device__ float g_prob[E_NUM*N_TOK];
__device__ __half g_xh [N_TOK*C_DIM];
__device__ __half g_w1h[E_NUM*C_DIM*H_DIM];   // native [e][c][h] = [k][n]
__device__ __half g_w2h[E_NUM*H_DIM*C_DIM];   // native [e][h][c] = [k][n]
__device__ __half g_hh [(size_t)NSEL*H_DIM];
__device__ float  g_outbuf[(size_t)NSEL*C_DIM];

// ---------------- low-level helpers (sm_80-era baseline) ----------------
__device__ __forceinline__ void cpa16(uint32_t dst, const void* src, uint32_t srcsz) {
    asm volatile("cp.async.cg.shared.global [%0], [%1], 16, %2;"
                 :: "r"(dst), "l"(src), "r"(srcsz) : "memory");
}
__device__ __forceinline__ void cpa_commit() {
    asm volatile("cp.async.commit_group;" ::: "memory");
}
template<int N>
__device__ __forceinline__ void cpa_wait() {
    asm volatile("cp.async.wait_group %0;" :: "n"(N) : "memory");
}
__device__ __forceinline__ void mma_f16(float* d, const uint32_t* a, const uint32_t* b) {
    asm volatile(
        "mma.sync.aligned.m16n8k16.row.col.f32.f16.f16.f32 "
        "{%0,%1,%2,%3}, {%4,%5,%6,%7}, {%8,%9}, {%0,%1,%2,%3};"
        : "+f"(d[0]), "+f"(d[1]), "+f"(d[2]), "+f"(d[3])
        : "r"(a[0]), "r"(a[1]), "r"(a[2]), "r"(a[3]), "r"(b[0]), "r"(b[1]));
}
__device__ __forceinline__ void ldsm_x4(uint32_t* r, uint32_t addr) {
    asm volatile("ldmatrix.sync.aligned.m8n8.x4.shared.b16 {%0,%1,%2,%3}, [%4];"
                 : "=r"(r[0]), "=r"(r[1]), "=r"(r[2]), "=r"(r[3]) : "r"(addr));
}
__device__ __forceinline__ void ldsm_x4_t(uint32_t* r, uint32_t addr) {
    asm volatile("ldmatrix.sync.aligned.m8n8.x4.trans.shared.b16 {%0,%1,%2,%3}, [%4];"
                 : "=r"(r[0]), "=r"(r[1]), "=r"(r[2]), "=r"(r[3]) : "r"(addr));
}

// SMEM geometry (LDSM conflict-free pitches: 144/16=9, 272/16=17 -> r mod 8)
#define A_PITCH 144
#define B_PITCH 272
#define A_BYTES (MT * A_PITCH)           // 18432
#define B_BYTES (KC * B_PITCH)           // 17408
#define OFF_B   A_BYTES
#define STAGE_B (A_BYTES + B_BYTES)      // 35840
#define NSTAGE  3
#define TILE0   2048
#define SMEM_SZ (TILE0 + NSTAGE * STAGE_B)   // 109568 (x2 CTAs = 219136 <= 228KB)

// prep kernel block ranges
#define WQUADS (E_NUM * C_DIM * H_DIM / 4)   // 4718592
#define WBLK   (WQUADS / 256)                // 18432
#define GATEBLK (N_TOK / 8)                  // 1024
#define XQUADS (N_TOK * C_DIM / 4)           // 1572864
#define XBLK   (XQUADS / 256)                // 6144
#define PREP_BLOCKS (2 * WBLK + GATEBLK + XBLK)  // 44032

// ---------------- kernel 0: zero counters ----------------
__global__ void zero_counts_kernel() {
    if (threadIdx.x < E_NUM) g_counts[threadIdx.x] = 0;
}

// ---------------- fused prep: convert w1 | convert w2 | gate | convert x ----
__global__ void prep_kernel(const float* __restrict__ x,
                            const float* __restrict__ gw,
                            const float* __restrict__ gb,
                            const float* __restrict__ w1,
                            const float* __restrict__ w2) {
    int b = blockIdx.x;
    int tid = threadIdx.x;

    if (b < 2 * WBLK) {
        // ---- weight convert (destination symbol chosen in device code) ----
        const float* in = (b < WBLK) ? w1 : w2;
        __half* o = (b < WBLK) ? g_w1h : g_w2h;
        size_t i = (size_t)(b < WBLK ? b : b - WBLK) * 256 + tid;
        float4 v = reinterpret_cast<const float4*>(in)[i];
        __half2* p = reinterpret_cast<__half2*>(o);
        p[i * 2 + 0] = __floats2half2_rn(v.x, v.y);
        p[i * 2 + 1] = __floats2half2_rn(v.z, v.w);
        return;
    }
    b -= 2 * WBLK;

    if (b < GATEBLK) {
        // ---- gate + top-2 routing (one warp/token) ----
        int warp = b * 8 + (tid >> 5);
        int lane = tid & 31;
        int token = warp;

        float acc[8];
#pragma unroll
        for (int e = 0; e < 8; e++) acc[e] = 0.f;

        const float* xr = x + (size_t)token * C_DIM;
#pragma unroll 4
        for (int c = lane; c < C_DIM; c += 32) {
            float xv = xr[c];
            const float4* g4 = reinterpret_cast<const float4*>(gw + (size_t)c * E_NUM);
            float4 g0 = g4[0];
            float4 g1 = g4[1];
            acc[0] += xv * g0.x; acc[1] += xv * g0.y;
            acc[2] += xv * g0.z; acc[3] += xv * g0.w;
            acc[4] += xv * g1.x; acc[5] += xv * g1.y;
            acc[6] += xv * g1.z; acc[7] += xv * g1.w;
        }
#pragma unroll
        for (int e = 0; e < 8; e++) {
#pragma unroll
            for (int off = 16; off > 0; off >>= 1)
                acc[e] += __shfl_xor_sync(0xffffffffu, acc[e], off);
        }

        if (lane == 0) {
            float best_v = -1e30f, sec_v = -1e30f;
            int best_e = 0, sec_e = 0;
#pragma unroll
            for (int e = 0; e < 8; e++) {
                float v = acc[e] + gb[e];
                if (v > best_v) { sec_v = best_v; sec_e = best_e; best_v = v; best_e = e; }
                else if (v > sec_v) { sec_v = v; sec_e = e; }
            }
            float z  = expf(sec_v - best_v);
            float p0 = 1.0f / (1.0f + z);
            float p1 = 1.0f - p0;

            int s0 = atomicAdd(&g_counts[best_e], 1);
            g_tok [best_e * N_TOK + s0] = token;
            g_hrow[best_e * N_TOK + s0] = token * 2;
            g_prob[best_e * N_TOK + s0] = p0;

            int s1 = atomicAdd(&g_counts[sec_e], 1);
            g_tok [sec_e * N_TOK + s1] = token;
            g_hrow[sec_e * N_TOK + s1] = token * 2 + 1;
            g_prob[sec_e * N_TOK + s1] = p1;
        }
        return;
    }
    b -= GATEBLK;

    // ---- cast x -> fp16 ----
    int i = b * 256 + tid;
    float4 v = reinterpret_cast<const float4*>(x)[i];
    __half2* p = reinterpret_cast<__half2*>(g_xh);
    p[i * 2 + 0] = __floats2half2_rn(v.x, v.y);
    p[i * 2 + 1] = __floats2half2_rn(v.z, v.w);
}

// ---------------- grouped GEMM: single-pass fp16 mma.sync ----------------
// D[128 sel rows, 128 n] = A @ B. 256 threads, 8 warps, warp 64x32.
// 2 CTAs/SM (decoupled pipelines). 3-stage cp.async, one sync per chunk.
template<int KDIM, bool IS_G1>
__global__ __launch_bounds__(256, 2)
void moe_gemm_kernel(const float* __restrict__ bias) {
    constexpr int NDIM = IS_G1 ? H_DIM : C_DIM;
    constexpr int NCH  = KDIM / KC;

    int e  = blockIdx.z;
    int ne = g_counts[e];
    int m0 = blockIdx.y * MT;
    if (m0 >= ne) return;
    int n0 = blockIdx.x * 128;

    extern __shared__ char smem[];
    int*   s_hrow = (int*)(smem);            // 512 B
    float* s_prob = (float*)(smem + 512);    // 512 B
    int*   s_gidx = (int*)(smem + 1024);     // 512 B

    int tid = threadIdx.x, wid = tid >> 5, lane = tid & 31;

    if (tid < MT) {
        int idx = m0 + tid;
        int g = -1, hr = -1; float p = 0.f;
        if (idx < ne) {
            g  = IS_G1 ? g_tok[e * N_TOK + idx] : g_hrow[e * N_TOK + idx];
            hr = g_hrow[e * N_TOK + idx];
            p  = g_prob[e * N_TOK + idx];
        }
        s_gidx[tid] = g;
        s_hrow[tid] = hr;
        s_prob[tid] = p;
    }
    __syncthreads();

    const __half* __restrict__ A = IS_G1 ? g_xh  : g_hh;
    const __half* __restrict__ B = IS_G1 ? g_w1h : g_w2h;

    // ---- loaders ----
    // A: thr t -> tile row t>>1 (0..127), 64B half t&1 (KC=64 fp16 = 128B/row)
    int arowi = tid >> 1, aq = tid & 1;
    int arow  = s_gidx[arowi];
    uint32_t asz = (arow >= 0) ? 16u : 0u;
    size_t abase = (size_t)(arow < 0 ? 0 : arow) * KDIM + aq * 32;
    uint32_t adst = arowi * A_PITCH + aq * 64;
    // B: thr t -> k-row t>>2 (0..63), 64B quarter t&3 (128 n fp16 = 256B/row)
    int bk = tid >> 2, bq = tid & 3;
    size_t bbase = ((size_t)e * KDIM) * NDIM + (size_t)bk * NDIM + n0 + bq * 32;
    uint32_t bdst = OFF_B + bk * B_PITCH + bq * 64;

    uint32_t tiles = (uint32_t)__cvta_generic_to_shared(smem + TILE0);

#define LOAD_CHUNK(cc, stg)                                                  \
    do {                                                                     \
        uint32_t sbb = tiles + (stg) * STAGE_B;                              \
        const __half* pA = A + abase + (size_t)(cc) * KC;                    \
        const __half* pB = B + bbase + (size_t)(cc) * KC * NDIM;             \
        cpa16(sbb + adst,      pA,      asz);                                \
        cpa16(sbb + adst + 16, pA + 8,  asz);                                \
        cpa16(sbb + adst + 32, pA + 16, asz);                                \
        cpa16(sbb + adst + 48, pA + 24, asz);                                \
        cpa16(sbb + bdst,      pB,      16u);                                \
        cpa16(sbb + bdst + 16, pB + 8,  16u);                                \
        cpa16(sbb + bdst + 32, pB + 16, 16u);                                \
        cpa16(sbb + bdst + 48, pB + 24, 16u);                                \
        cpa_commit();                                                        \
    } while (0)

    LOAD_CHUNK(0, 0);
    LOAD_CHUNK(1, 1);

    // ---- compute mapping: 8 warps, wm = wid>>2 (rows wm*64), wn = wid&3 ----
    int wm = wid >> 2, wn = wid & 3;
    int lr = lane >> 2, lc2 = (lane & 3) * 2;

    int q8  = (lane & 7) + ((lane >> 3) & 1) * 8;   // LDSM row within 16-block
    int qk  = (lane >> 4) & 1;                       // second 16B column
    uint32_t aoff[4];
#pragma unroll
    for (int mt = 0; mt < 4; mt++)
        aoff[mt] = (uint32_t)((wm * 64 + mt * 16 + q8) * A_PITCH + qk * 16);
    uint32_t boff[2];
#pragma unroll
    for (int p = 0; p < 2; p++)
        boff[p] = (uint32_t)(OFF_B + q8 * B_PITCH + (wn * 32 + p * 16) * 2 + qk * 16);

    float acc[4][4][4];
#pragma unroll
    for (int mt = 0; mt < 4; mt++)
#pragma unroll
        for (int nt = 0; nt < 4; nt++)
#pragma unroll
            for (int q = 0; q < 4; q++) acc[mt][nt][q] = 0.f;

    int s_cur = 0, s_ld = 2;   // compute stage / stage for chunk c+2
    for (int c = 0; c < NCH; c++) {
        if (c + 1 < NCH) { cpa_wait<1>(); } else { cpa_wait<0>(); }
        __syncthreads();   // all warps done reading stage s_ld's previous tenant
        if (c + 2 < NCH) LOAD_CHUNK(c + 2, s_ld);

        uint32_t sb = tiles + s_cur * STAGE_B;
#pragma unroll
        for (int ks = 0; ks < KC / 16; ks++) {
            uint32_t ah[4][4];
#pragma unroll
            for (int mt = 0; mt < 4; mt++)
                ldsm_x4(ah[mt], sb + aoff[mt] + ks * 32);

            uint32_t bf[4][2];
#pragma unroll
            for (int p = 0; p < 2; p++) {
                uint32_t t4[4];
                ldsm_x4_t(t4, sb + boff[p] + ks * 16 * B_PITCH);
                // quads: 0=(k0-7,n0-7) 1=(k8-15,n0-7) 2=(k0-7,n8-15) 3=(k8-15,n8-15)
                bf[2*p + 0][0] = t4[0]; bf[2*p + 0][1] = t4[1];
                bf[2*p + 1][0] = t4[2]; bf[2*p + 1][1] = t4[3];
            }
#pragma unroll
            for (int mt = 0; mt < 4; mt++)
#pragma unroll
                for (int nt = 0; nt < 4; nt++)
                    mma_f16(acc[mt][nt], ah[mt], bf[nt]);
        }
        s_cur = (s_cur == 2) ? 0 : s_cur + 1;
        s_ld  = (s_ld  == 2) ? 0 : s_ld  + 1;
    }

    // ---- epilogue ----
#pragma unroll
    for (int nt = 0; nt < 4; nt++) {
        int col = n0 + wn * 32 + nt * 8 + lc2;
        float bb0 = bias[(size_t)e * NDIM + col];
        float bb1 = bias[(size_t)e * NDIM + col + 1];
#pragma unroll
        for (int mt = 0; mt < 4; mt++) {
            int r0 = wm * 64 + mt * 16 + lr;
#pragma unroll
            for (int rh = 0; rh < 2; rh++) {
                int rr = r0 + rh * 8;
                int hr = s_hrow[rr];
                if (hr < 0) continue;
                float v0 = acc[mt][nt][rh * 2 + 0] + bb0;
                float v1 = acc[mt][nt][rh * 2 + 1] + bb1;
                if (IS_G1) {
                    v0 = 0.5f * v0 * (1.0f + erff(v0 * 0.70710678118654752f));
                    v1 = 0.5f * v1 * (1.0f + erff(v1 * 0.70710678118654752f));
                    *(__half2*)(g_hh + (size_t)hr * H_DIM + col) =
                        __floats2half2_rn(v0, v1);
                } else {
                    float p = s_prob[rr];
                    *(float2*)(g_outbuf + (size_t)hr * C_DIM + col) =
                        make_float2(v0 * p, v1 * p);
                }
            }
        }
    }
}

// ---------------- kernel: combine top-2 contributions (float4) ----------------
__global__ void combine_kernel(float* __restrict__ out) {
    int i = blockIdx.x * blockDim.x + threadIdx.x;   // over N_TOK*C_DIM/4
    int t  = i / (C_DIM / 4);
    int c4 = i - t * (C_DIM / 4);
    float4 a = *((const float4*)(g_outbuf + (size_t)(2 * t)     * C_DIM) + c4);
    float4 b = *((const float4*)(g_outbuf + (size_t)(2 * t + 1) * C_DIM) + c4);
    reinterpret_cast<float4*>(out)[i] =
        make_float4(a.x + b.x, a.y + b.y, a.z + b.z, a.w + b.w);
}

// ---------------- launcher ----------------
extern "C" void kernel_launch(void* const* d_in, const int* in_sizes, int n_in,
                              void* d_out, int out_size) {
    const float* x      = (const float*)d_in[0];
    const float* gate_w = (const float*)d_in[1];
    const float* gate_b = (const float*)d_in[2];
    const float* w1     = (const float*)d_in[3];
    const float* b1     = (const float*)d_in[4];
    const float* w2     = (const float*)d_in[5];
    const float* b2     = (const float*)d_in[6];
    float* out = (float*)d_out;

    cudaFuncSetAttribute(moe_gemm_kernel<C_DIM, true>,
                         cudaFuncAttributeMaxDynamicSharedMemorySize, SMEM_SZ);
    cudaFuncSetAttribute(moe_gemm_kernel<H_DIM, false>,
                         cudaFuncAttributeMaxDynamicSharedMemorySize, SMEM_SZ);

    zero_counts_kernel<<<1, 32>>>();
    prep_kernel<<<PREP_BLOCKS, 256>>>(x, gate_w, gate_b, w1, w2);

    dim3 g1(H_DIM / 128, N_TOK / MT, E_NUM);   // (24, 64, 8)
    moe_gemm_kernel<C_DIM, true><<<g1, 256, SMEM_SZ>>>(b1);

    dim3 g2(C_DIM / 128, N_TOK / MT, E_NUM);   // (6, 64, 8)
    moe_gemm_kernel<H_DIM, false><<<g2, 256, SMEM_SZ>>>(b2);

    combine_kernel<<<(N_TOK * C_DIM / 4) / 256, 256>>>(out);
}

// round 12
// speedup vs baseline: 1.2153x; 1.2153x over previous
#include <cuda_runtime.h>
#include <cuda_fp16.h>
#include <math.h>
#include <stdint.h>

#define N_TOK 8192
#define C_DIM 768
#define E_NUM 8
#define H_DIM 3072
#define NSEL  (2*N_TOK)
#define KC    64
#define MT    128          // M tile (sel rows per block)

// ---------------- device scratch (no runtime allocation) ----------------
__device__ int   g_counts[E_NUM];
__device__ int   g_tok [E_NUM*N_TOK];
__device__ int   g_hrow[E_NUM*N_TOK];
__device__ float g_prob[E_NUM*N_TOK];
__device__ __half g_xh [N_TOK*C_DIM];
__device__ __half g_w1h[E_NUM*C_DIM*H_DIM];   // native [e][c][h] = [k][n]
__device__ __half g_w2h[E_NUM*H_DIM*C_DIM];   // native [e][h][c] = [k][n]
__device__ __half g_hh [(size_t)NSEL*H_DIM];
__device__ float  g_outbuf[(size_t)NSEL*C_DIM];

// ---------------- low-level helpers (sm_80-era baseline) ----------------
__device__ __forceinline__ void cpa16(uint32_t dst, const void* src, uint32_t srcsz) {
    asm volatile("cp.async.cg.shared.global [%0], [%1], 16, %2;"
                 :: "r"(dst), "l"(src), "r"(srcsz) : "memory");
}
__device__ __forceinline__ void cpa_commit() {
    asm volatile("cp.async.commit_group;" ::: "memory");
}
template<int N>
__device__ __forceinline__ void cpa_wait() {
    asm volatile("cp.async.wait_group %0;" :: "n"(N) : "memory");
}
__device__ __forceinline__ void mma_f16(float* d, const uint32_t* a, const uint32_t* b) {
    asm volatile(
        "mma.sync.aligned.m16n8k16.row.col.f32.f16.f16.f32 "
        "{%0,%1,%2,%3}, {%4,%5,%6,%7}, {%8,%9}, {%0,%1,%2,%3};"
        : "+f"(d[0]), "+f"(d[1]), "+f"(d[2]), "+f"(d[3])
        : "r"(a[0]), "r"(a[1]), "r"(a[2]), "r"(a[3]), "r"(b[0]), "r"(b[1]));
}
__device__ __forceinline__ void ldsm_x4(uint32_t* r, uint32_t addr) {
    asm volatile("ldmatrix.sync.aligned.m8n8.x4.shared.b16 {%0,%1,%2,%3}, [%4];"
                 : "=r"(r[0]), "=r"(r[1]), "=r"(r[2]), "=r"(r[3]) : "r"(addr));
}
__device__ __forceinline__ void ldsm_x4_t(uint32_t* r, uint32_t addr) {
    asm volatile("ldmatrix.sync.aligned.m8n8.x4.trans.shared.b16 {%0,%1,%2,%3}, [%4];"
                 : "=r"(r[0]), "=r"(r[1]), "=r"(r[2]), "=r"(r[3]) : "r"(addr));
}

// SMEM geometry (LDSM conflict-free pitches: 144/16=9, 272/16=17 -> r mod 8)
#define A_PITCH 144
#define B_PITCH 272
#define A_BYTES (MT * A_PITCH)           // 18432
#define B_BYTES (KC * B_PITCH)           // 17408
#define OFF_B   A_BYTES
#define STAGE_B (A_BYTES + B_BYTES)      // 35840
#define NSTAGE  3
#define TILE0   2048
#define SMEM_SZ (TILE0 + NSTAGE * STAGE_B)   // 109568 (x2 CTAs = 219136 <= 228KB)

// prep kernel block ranges
#define WQUADS (E_NUM * C_DIM * H_DIM / 4)   // 4718592
#define WBLK   (WQUADS / 256)                // 18432
#define GATEBLK (N_TOK / 8)                  // 1024
#define XQUADS (N_TOK * C_DIM / 4)           // 1572864
#define XBLK   (XQUADS / 256)                // 6144
#define PREP_BLOCKS (2 * WBLK + GATEBLK + XBLK)  // 44032

// ---------------- kernel 0: zero counters ----------------
__global__ void zero_counts_kernel() {
    if (threadIdx.x < E_NUM) g_counts[threadIdx.x] = 0;
}

// ---------------- fused prep: convert w1 | convert w2 | gate | convert x ----
__global__ void prep_kernel(const float* __restrict__ x,
                            const float* __restrict__ gw,
                            const float* __restrict__ gb,
                            const float* __restrict__ w1,
                            const float* __restrict__ w2) {
    int b = blockIdx.x;
    int tid = threadIdx.x;

    if (b < 2 * WBLK) {
        // ---- weight convert (destination symbol chosen in device code) ----
        const float* in = (b < WBLK) ? w1 : w2;
        __half* o = (b < WBLK) ? g_w1h : g_w2h;
        size_t i = (size_t)(b < WBLK ? b : b - WBLK) * 256 + tid;
        float4 v = reinterpret_cast<const float4*>(in)[i];
        __half2* p = reinterpret_cast<__half2*>(o);
        p[i * 2 + 0] = __floats2half2_rn(v.x, v.y);
        p[i * 2 + 1] = __floats2half2_rn(v.z, v.w);
        return;
    }
    b -= 2 * WBLK;

    if (b < GATEBLK) {
        // ---- gate + top-2 routing (one warp/token) ----
        int warp = b * 8 + (tid >> 5);
        int lane = tid & 31;
        int token = warp;

        float acc[8];
#pragma unroll
        for (int e = 0; e < 8; e++) acc[e] = 0.f;

        const float* xr = x + (size_t)token * C_DIM;
#pragma unroll 4
        for (int c = lane; c < C_DIM; c += 32) {
            float xv = xr[c];
            const float4* g4 = reinterpret_cast<const float4*>(gw + (size_t)c * E_NUM);
            float4 g0 = g4[0];
            float4 g1 = g4[1];
            acc[0] += xv * g0.x; acc[1] += xv * g0.y;
            acc[2] += xv * g0.z; acc[3] += xv * g0.w;
            acc[4] += xv * g1.x; acc[5] += xv * g1.y;
            acc[6] += xv * g1.z; acc[7] += xv * g1.w;
        }
#pragma unroll
        for (int e = 0; e < 8; e++) {
#pragma unroll
            for (int off = 16; off > 0; off >>= 1)
                acc[e] += __shfl_xor_sync(0xffffffffu, acc[e], off);
        }

        if (lane == 0) {
            float best_v = -1e30f, sec_v = -1e30f;
            int best_e = 0, sec_e = 0;
#pragma unroll
            for (int e = 0; e < 8; e++) {
                float v = acc[e] + gb[e];
                if (v > best_v) { sec_v = best_v; sec_e = best_e; best_v = v; best_e = e; }
                else if (v > sec_v) { sec_v = v; sec_e = e; }
            }
            float z  = expf(sec_v - best_v);
            float p0 = 1.0f / (1.0f + z);
            float p1 = 1.0f - p0;

            int s0 = atomicAdd(&g_counts[best_e], 1);
            g_tok [best_e * N_TOK + s0] = token;
            g_hrow[best_e * N_TOK + s0] = token * 2;
            g_prob[best_e * N_TOK + s0] = p0;

            int s1 = atomicAdd(&g_counts[sec_e], 1);
            g_tok [sec_e * N_TOK + s1] = token;
            g_hrow[sec_e * N_TOK + s1] = token * 2 + 1;
            g_prob[sec_e * N_TOK + s1] = p1;
        }
        return;
    }
    b -= GATEBLK;

    // ---- cast x -> fp16 ----
    int i = b * 256 + tid;
    float4 v = reinterpret_cast<const float4*>(x)[i];
    __half2* p = reinterpret_cast<__half2*>(g_xh);
    p[i * 2 + 0] = __floats2half2_rn(v.x, v.y);
    p[i * 2 + 1] = __floats2half2_rn(v.z, v.w);
}

// ---------------- grouped GEMM: single-pass fp16 mma.sync ----------------
// D[128 sel rows, 128 n] = A @ B. 512 threads, 16 warps, warp tile 32x32.
// <=64 regs/thread -> 2 CTAs/SM = 32 warps/SM (8/SMSP) for latency hiding.
// 3-stage cp.async, one sync per chunk.
template<int KDIM, bool IS_G1>
__global__ __launch_bounds__(512, 2)
void moe_gemm_kernel(const float* __restrict__ bias) {
    constexpr int NDIM = IS_G1 ? H_DIM : C_DIM;
    constexpr int NCH  = KDIM / KC;

    int e  = blockIdx.z;
    int ne = g_counts[e];
    int m0 = blockIdx.y * MT;
    if (m0 >= ne) return;
    int n0 = blockIdx.x * 128;

    extern __shared__ char smem[];
    int*   s_hrow = (int*)(smem);            // 512 B
    float* s_prob = (float*)(smem + 512);    // 512 B
    int*   s_gidx = (int*)(smem + 1024);     // 512 B

    int tid = threadIdx.x, wid = tid >> 5, lane = tid & 31;

    if (tid < MT) {
        int idx = m0 + tid;
        int g = -1, hr = -1; float p = 0.f;
        if (idx < ne) {
            g  = IS_G1 ? g_tok[e * N_TOK + idx] : g_hrow[e * N_TOK + idx];
            hr = g_hrow[e * N_TOK + idx];
            p  = g_prob[e * N_TOK + idx];
        }
        s_gidx[tid] = g;
        s_hrow[tid] = hr;
        s_prob[tid] = p;
    }
    __syncthreads();

    const __half* __restrict__ A = IS_G1 ? g_xh  : g_hh;
    const __half* __restrict__ B = IS_G1 ? g_w1h : g_w2h;

    // ---- loaders (512 threads) ----
    // A: thr t -> tile row t>>2 (0..127), 32B quarter t&3 (128B/row)
    int arowi = tid >> 2, aq = tid & 3;
    int arow  = s_gidx[arowi];
    uint32_t asz = (arow >= 0) ? 16u : 0u;
    size_t abase = (size_t)(arow < 0 ? 0 : arow) * KDIM + aq * 16;
    uint32_t adst = arowi * A_PITCH + aq * 32;
    // B: thr t -> k-row t>>3 (0..63), 32B eighth t&7 (256B/row)
    int bk = tid >> 3, bq = tid & 7;
    size_t bbase = ((size_t)e * KDIM) * NDIM + (size_t)bk * NDIM + n0 + bq * 16;
    uint32_t bdst = OFF_B + bk * B_PITCH + bq * 32;

    uint32_t tiles = (uint32_t)__cvta_generic_to_shared(smem + TILE0);

#define LOAD_CHUNK(cc, stg)                                                  \
    do {                                                                     \
        uint32_t sbb = tiles + (stg) * STAGE_B;                              \
        const __half* pA = A + abase + (size_t)(cc) * KC;                    \
        const __half* pB = B + bbase + (size_t)(cc) * KC * NDIM;             \
        cpa16(sbb + adst,      pA,     asz);                                 \
        cpa16(sbb + adst + 16, pA + 8, asz);                                 \
        cpa16(sbb + bdst,      pB,     16u);                                 \
        cpa16(sbb + bdst + 16, pB + 8, 16u);                                 \
        cpa_commit();                                                        \
    } while (0)

    LOAD_CHUNK(0, 0);
    LOAD_CHUNK(1, 1);

    // ---- compute mapping: 16 warps, warp tile 32x32 ----
    // wm = wid>>2 (rows wm*32), wn = wid&3 (cols wn*32)
    int wm = wid >> 2, wn = wid & 3;
    int lr = lane >> 2, lc2 = (lane & 3) * 2;

    int q8  = (lane & 7) + ((lane >> 3) & 1) * 8;   // LDSM row within 16-block
    int qk  = (lane >> 4) & 1;                       // second 16B column
    uint32_t aoff[2];
#pragma unroll
    for (int mt = 0; mt < 2; mt++)
        aoff[mt] = (uint32_t)((wm * 32 + mt * 16 + q8) * A_PITCH + qk * 16);
    uint32_t boff[2];
#pragma unroll
    for (int p = 0; p < 2; p++)
        boff[p] = (uint32_t)(OFF_B + q8 * B_PITCH + (wn * 32 + p * 16) * 2 + qk * 16);

    float acc[2][4][4];
#pragma unroll
    for (int mt = 0; mt < 2; mt++)
#pragma unroll
        for (int nt = 0; nt < 4; nt++)
#pragma unroll
            for (int q = 0; q < 4; q++) acc[mt][nt][q] = 0.f;

    int s_cur = 0, s_ld = 2;   // compute stage / stage for chunk c+2
    for (int c = 0; c < NCH; c++) {
        if (c + 1 < NCH) { cpa_wait<1>(); } else { cpa_wait<0>(); }
        __syncthreads();   // all warps done reading stage s_ld's previous tenant
        if (c + 2 < NCH) LOAD_CHUNK(c + 2, s_ld);

        uint32_t sb = tiles + s_cur * STAGE_B;
#pragma unroll
        for (int ks = 0; ks < KC / 16; ks++) {
            uint32_t ah[2][4];
#pragma unroll
            for (int mt = 0; mt < 2; mt++)
                ldsm_x4(ah[mt], sb + aoff[mt] + ks * 32);

            uint32_t bf[4][2];
#pragma unroll
            for (int p = 0; p < 2; p++) {
                uint32_t t4[4];
                ldsm_x4_t(t4, sb + boff[p] + ks * 16 * B_PITCH);
                // quads: 0=(k0-7,n0-7) 1=(k8-15,n0-7) 2=(k0-7,n8-15) 3=(k8-15,n8-15)
                bf[2*p + 0][0] = t4[0]; bf[2*p + 0][1] = t4[1];
                bf[2*p + 1][0] = t4[2]; bf[2*p + 1][1] = t4[3];
            }
#pragma unroll
            for (int mt = 0; mt < 2; mt++)
#pragma unroll
                for (int nt = 0; nt < 4; nt++)
                    mma_f16(acc[mt][nt], ah[mt], bf[nt]);
        }
        s_cur = (s_cur == 2) ? 0 : s_cur + 1;
        s_ld  = (s_ld  == 2) ? 0 : s_ld  + 1;
    }

    // ---- epilogue ----
#pragma unroll
    for (int nt = 0; nt < 4; nt++) {
        int col = n0 + wn * 32 + nt * 8 + lc2;
        float bb0 = bias[(size_t)e * NDIM + col];
        float bb1 = bias[(size_t)e * NDIM + col + 1];
#pragma unroll
        for (int mt = 0; mt < 2; mt++) {
            int r0 = wm * 32 + mt * 16 + lr;
#pragma unroll
            for (int rh = 0; rh < 2; rh++) {
                int rr = r0 + rh * 8;
                int hr = s_hrow[rr];
                if (hr < 0) continue;
                float v0 = acc[mt][nt][rh * 2 + 0] + bb0;
                float v1 = acc[mt][nt][rh * 2 + 1] + bb1;
                if (IS_G1) {
                    v0 = 0.5f * v0 * (1.0f + erff(v0 * 0.70710678118654752f));
                    v1 = 0.5f * v1 * (1.0f + erff(v1 * 0.70710678118654752f));
                    *(__half2*)(g_hh + (size_t)hr * H_DIM + col) =
                        __floats2half2_rn(v0, v1);
                } else {
                    float p = s_prob[rr];
                    *(float2*)(g_outbuf + (size_t)hr * C_DIM + col) =
                        make_float2(v0 * p, v1 * p);
                }
            }
        }
    }
}

// ---------------- kernel: combine top-2 contributions (float4) ----------------
__global__ void combine_kernel(float* __restrict__ out) {
    int i = blockIdx.x * blockDim.x + threadIdx.x;   // over N_TOK*C_DIM/4
    int t  = i / (C_DIM / 4);
    int c4 = i - t * (C_DIM / 4);
    float4 a = *((const float4*)(g_outbuf + (size_t)(2 * t)     * C_DIM) + c4);
    float4 b = *((const float4*)(g_outbuf + (size_t)(2 * t + 1) * C_DIM) + c4);
    reinterpret_cast<float4*>(out)[i] =
        make_float4(a.x + b.x, a.y + b.y, a.z + b.z, a.w + b.w);
}

// ---------------- launcher ----------------
extern "C" void kernel_launch(void* const* d_in, const int* in_sizes, int n_in,
                              void* d_out, int out_size) {
    const float* x      = (const float*)d_in[0];
    const float* gate_w = (const float*)d_in[1];
    const float* gate_b = (const float*)d_in[2];
    const float* w1     = (const float*)d_in[3];
    const float* b1     = (const float*)d_in[4];
    const float* w2     = (const float*)d_in[5];
    const float* b2     = (const float*)d_in[6];
    float* out = (float*)d_out;

    cudaFuncSetAttribute(moe_gemm_kernel<C_DIM, true>,
                         cudaFuncAttributeMaxDynamicSharedMemorySize, SMEM_SZ);
    cudaFuncSetAttribute(moe_gemm_kernel<H_DIM, false>,
                         cudaFuncAttributeMaxDynamicSharedMemorySize, SMEM_SZ);

    zero_counts_kernel<<<1, 32>>>();
    prep_kernel<<<PREP_BLOCKS, 256>>>(x, gate_w, gate_b, w1, w2);

    dim3 g1(H_DIM / 128, N_TOK / MT, E_NUM);   // (24, 64, 8)
    moe_gemm_kernel<C_DIM, true><<<g1, 512, SMEM_SZ>>>(b1);

    dim3 g2(C_DIM / 128, N_TOK / MT, E_NUM);   // (6, 64, 8)
    moe_gemm_kernel<H_DIM, false><<<g2, 512, SMEM_SZ>>>(b2);

    combine_kernel<<<(N_TOK * C_DIM / 4) / 256, 256>>>(out);
}